// round 2
// baseline (speedup 1.0000x reference)
#include <cuda_runtime.h>
#include <math.h>

// Problem constants
#define BATCH 64
#define NSEP  6
#define SLEN  256
#define TLEN  64
#define DMODEL 512
#define NHEAD 4
#define DHEAD 128
#define FFDIM 512
#define NLAYER 4
#define IMGDIM 2048

#define MAIN_TOK (BATCH*SLEN)          // 16384
#define HIST_SEQ (BATCH*NSEP)          // 384
#define HIST_TOK (HIST_SEQ*TLEN)       // 24576
#define MAXTOK   HIST_TOK

// ---------------- scratch (device globals; no allocation allowed) ------------
__device__ float g_x [MAXTOK*DMODEL];
__device__ float g_q [MAXTOK*DMODEL];
__device__ float g_k [MAXTOK*DMODEL];
__device__ float g_v [MAXTOK*DMODEL];
__device__ float g_t1[MAXTOK*DMODEL];
__device__ float g_t2[MAXTOK*DMODEL];
__device__ float g_hidden[BATCH*DMODEL];
__device__ float g_sep[HIST_SEQ*DMODEL];

// ---------------- generic SGEMM: C = A[M,K] @ W[K,N] + bias, opt ReLU --------
// 64x64x16 tile, 256 threads, 4x4 microtile. K,N assumed multiples of 16/64
// (true for all call sites: K in {512,2048}, N = 512). M padded by predication.
#define GBM 64
#define GBN 64
#define GBK 16
#define GTM 4
#define GTN 4

__global__ void gemm_bias(const float* __restrict__ A, const float* __restrict__ W,
                          const float* __restrict__ bias, float* __restrict__ C,
                          int M, int N, int K, int relu)
{
    __shared__ float As[GBK][GBM + 1];   // padded: conflict-free transposed stores
    __shared__ float Bs[GBK][GBN];

    int tid = threadIdx.x;                 // 256 threads
    int brow = blockIdx.y * GBM;
    int bcol = blockIdx.x * GBN;
    int tr = (tid / (GBN / GTN)) * GTM;    // 0..60 step 4
    int tc = (tid % (GBN / GTN)) * GTN;

    float acc[GTM][GTN];
    #pragma unroll
    for (int i = 0; i < GTM; i++)
        #pragma unroll
        for (int j = 0; j < GTN; j++) acc[i][j] = 0.f;

    // A-load mapping: thread -> (mm = tid/4, kk = 4*(tid%4)), float4 along K
    int a_mm = tid >> 2;
    int a_kk = (tid & 3) << 2;
    // W-load mapping: thread -> (kk = tid/16, nn = 4*(tid%16)), float4 along N
    int b_kk = tid >> 4;
    int b_nn = (tid & 15) << 2;

    for (int k0 = 0; k0 < K; k0 += GBK) {
        // load A tile (64 x 16): one float4 per thread
        {
            int row = brow + a_mm;
            float4 a4 = make_float4(0.f, 0.f, 0.f, 0.f);
            if (row < M)
                a4 = *(const float4*)(A + (size_t)row * K + k0 + a_kk);
            As[a_kk + 0][a_mm] = a4.x;
            As[a_kk + 1][a_mm] = a4.y;
            As[a_kk + 2][a_mm] = a4.z;
            As[a_kk + 3][a_mm] = a4.w;
        }
        // load W tile (16 x 64): one float4 per thread
        {
            float4 b4 = *(const float4*)(W + (size_t)(k0 + b_kk) * N + bcol + b_nn);
            *(float4*)(&Bs[b_kk][b_nn]) = b4;
        }
        __syncthreads();

        #pragma unroll
        for (int kk = 0; kk < GBK; kk++) {
            float a[GTM], b[GTN];
            #pragma unroll
            for (int i = 0; i < GTM; i++) a[i] = As[kk][tr + i];
            #pragma unroll
            for (int j = 0; j < GTN; j++) b[j] = Bs[kk][tc + j];
            #pragma unroll
            for (int i = 0; i < GTM; i++)
                #pragma unroll
                for (int j = 0; j < GTN; j++) acc[i][j] += a[i] * b[j];
        }
        __syncthreads();
    }

    #pragma unroll
    for (int i = 0; i < GTM; i++) {
        int row = brow + tr + i;
        if (row >= M) continue;
        #pragma unroll
        for (int j = 0; j < GTN; j++) {
            int col = bcol + tc + j;
            float val = acc[i][j] + bias[col];
            if (relu) val = fmaxf(val, 0.f);
            C[(size_t)row * N + col] = val;
        }
    }
}

// ---------------- attention: one block per (m, h, q-row), 128 threads --------
__global__ void attn_kernel(const float* __restrict__ q, const float* __restrict__ k,
                            const float* __restrict__ v, float* __restrict__ out,
                            const int* __restrict__ lens, int Tt)
{
    int idx = blockIdx.x;
    int qi = idx % Tt; idx /= Tt;
    int h  = idx % NHEAD; idx /= NHEAD;
    int m  = idx;

    int tid = threadIdx.x;
    int lane = tid & 31, warp = tid >> 5;

    __shared__ float qs[DHEAD];
    __shared__ float sc[SLEN];     // Tt <= 256
    __shared__ float red[4];

    const float* qrow = q + ((size_t)(m * Tt + qi)) * DMODEL + h * DHEAD;
    if (tid < DHEAD) qs[tid] = qrow[tid];
    int valid = Tt;
    if (lens) { int l = lens[m]; valid = l > 1 ? l : 1; }
    __syncthreads();

    // scores: warp per key
    for (int j = warp; j < Tt; j += 4) {
        const float* krow = k + ((size_t)(m * Tt + j)) * DMODEL + h * DHEAD;
        float p = 0.f;
        #pragma unroll
        for (int d = lane; d < DHEAD; d += 32) p += qs[d] * krow[d];
        #pragma unroll
        for (int o = 16; o; o >>= 1) p += __shfl_xor_sync(0xffffffffu, p, o);
        if (lane == 0)
            sc[j] = (j < valid) ? p * 0.08838834764831845f : -1e9f;   // 1/sqrt(128)
    }
    __syncthreads();

    // softmax max
    float mx = -1e30f;
    for (int j = tid; j < Tt; j += 128) mx = fmaxf(mx, sc[j]);
    #pragma unroll
    for (int o = 16; o; o >>= 1) mx = fmaxf(mx, __shfl_xor_sync(0xffffffffu, mx, o));
    if (lane == 0) red[warp] = mx;
    __syncthreads();
    mx = fmaxf(fmaxf(red[0], red[1]), fmaxf(red[2], red[3]));
    __syncthreads();   // protect red reuse

    float sum = 0.f;
    for (int j = tid; j < Tt; j += 128) { float e = __expf(sc[j] - mx); sc[j] = e; sum += e; }
    #pragma unroll
    for (int o = 16; o; o >>= 1) sum += __shfl_xor_sync(0xffffffffu, sum, o);
    if (lane == 0) red[warp] = sum;
    __syncthreads();
    sum = red[0] + red[1] + red[2] + red[3];
    float inv = 1.f / sum;

    // ctx: one channel per thread
    int d = tid;
    if (d < DHEAD) {
        const float* vcol = v + ((size_t)m * Tt) * DMODEL + h * DHEAD + d;
        float acc = 0.f;
        for (int j = 0; j < Tt; j++) acc += sc[j] * vcol[(size_t)j * DMODEL];
        out[((size_t)(m * Tt + qi)) * DMODEL + h * DHEAD + d] = acc * inv;
    }
}

// ---------------- residual add + LayerNorm, block per token -----------------
__global__ void add_ln_kernel(const float* __restrict__ x, const float* __restrict__ y,
                              const float* __restrict__ g, const float* __restrict__ b,
                              float* __restrict__ out)
{
    int t = blockIdx.x, tid = threadIdx.x;
    const float* xr = x + (size_t)t * DMODEL;
    const float* yr = y + (size_t)t * DMODEL;
    int lane = tid & 31, warp = tid >> 5;
    __shared__ float red[4];

    float h[4];
    float s = 0.f;
    #pragma unroll
    for (int i = 0; i < 4; i++) { int d = tid + i * 128; h[i] = xr[d] + yr[d]; s += h[i]; }
    #pragma unroll
    for (int o = 16; o; o >>= 1) s += __shfl_xor_sync(0xffffffffu, s, o);
    if (lane == 0) red[warp] = s;
    __syncthreads();
    s = red[0] + red[1] + red[2] + red[3];
    float mu = s * (1.f / DMODEL);

    float vs = 0.f;
    #pragma unroll
    for (int i = 0; i < 4; i++) { float dl = h[i] - mu; vs += dl * dl; }
    #pragma unroll
    for (int o = 16; o; o >>= 1) vs += __shfl_xor_sync(0xffffffffu, vs, o);
    __syncthreads();   // red reuse
    if (lane == 0) red[warp] = vs;
    __syncthreads();
    vs = (red[0] + red[1] + red[2] + red[3]) * (1.f / DMODEL);
    float invstd = rsqrtf(vs + 1e-5f);

    float* orow = out + (size_t)t * DMODEL;
    #pragma unroll
    for (int i = 0; i < 4; i++) {
        int d = tid + i * 128;
        orow[d] = (h[i] - mu) * invstd * g[d] + b[d];
    }
}

// ---------------- embedding + positional encoding ---------------------------
__device__ __forceinline__ float pe_val(int pos, int d)
{
    int i2 = d & ~1;                       // 2*(d/2)
    float div = expf((float)i2 * (-9.210340371976184f / (float)DMODEL));
    float ang = (float)pos * div;
    return (d & 1) ? cosf(ang) : sinf(ang);
}

__global__ void embed_kernel(const int* __restrict__ ids, const float* __restrict__ emb,
                             float* __restrict__ x, int seqlen)
{
    int tok = blockIdx.x;
    int pos = tok % seqlen;
    int id = ids[tok];
    const float* erow = emb + (size_t)id * DMODEL;
    float* xrow = x + (size_t)tok * DMODEL;
    for (int d = threadIdx.x; d < DMODEL; d += 128)
        xrow[d] = erow[d] + pe_val(pos, d);
}

// ---------------- small epilogue kernels -------------------------------------
__global__ void copy_hidden_kernel(const float* __restrict__ x, float* __restrict__ hid)
{
    int b = blockIdx.x;
    const float* src = x + ((size_t)(b * SLEN + SLEN - 1)) * DMODEL;
    for (int d = threadIdx.x; d < DMODEL; d += 128)
        hid[b * DMODEL + d] = src[d];
}

__global__ void gather_add_kernel(const float* __restrict__ hx, const int* __restrict__ lens,
                                  float* __restrict__ sep)
{
    int r = blockIdx.x;
    int len = lens[r];
    if (len <= 0) return;
    const float* src = hx + ((size_t)(r * TLEN + len - 1)) * DMODEL;
    for (int d = threadIdx.x; d < DMODEL; d += 128)
        sep[(size_t)r * DMODEL + d] += src[d];
}

__global__ void final_kernel(const float* __restrict__ sep, const float* __restrict__ hidden,
                             const int* __restrict__ normalize, float* __restrict__ out)
{
    int r = blockIdx.x;            // 0..383
    int b = r / NSEP;
    int tid = threadIdx.x;
    int lane = tid & 31, warp = tid >> 5;
    int norm = *normalize;

    __shared__ float sbuf[DMODEL];
    __shared__ float red[4];

    for (int d = tid; d < DMODEL; d += 128) {
        float v = sep[(size_t)r * DMODEL + d];
        if (norm) v = fmaxf(v, 0.f);
        sbuf[d] = v;
    }
    __syncthreads();

    float scale = 1.f;
    if (norm) {
        float ss = 0.f;
        for (int d = tid; d < DMODEL; d += 128) ss += sbuf[d] * sbuf[d];
        #pragma unroll
        for (int o = 16; o; o >>= 1) ss += __shfl_xor_sync(0xffffffffu, ss, o);
        if (lane == 0) red[warp] = ss;
        __syncthreads();
        ss = red[0] + red[1] + red[2] + red[3];
        float nrm = sqrtf(ss);
        scale = 1.f / fmaxf(nrm, 1e-12f);
        __syncthreads();   // red reuse below
    }

    float dp = 0.f;
    for (int d = tid; d < DMODEL; d += 128)
        dp += sbuf[d] * scale * hidden[(size_t)b * DMODEL + d];
    #pragma unroll
    for (int o = 16; o; o >>= 1) dp += __shfl_xor_sync(0xffffffffu, dp, o);
    if (lane == 0) red[warp] = dp;
    __syncthreads();
    if (tid == 0) out[r] = red[0] + red[1] + red[2] + red[3];
}

// ---------------- host side ---------------------------------------------------
static void gemm(const float* A, const float* W, const float* bias, float* C,
                 int M, int N, int K, int relu)
{
    dim3 grid(N / GBN, (M + GBM - 1) / GBM);
    gemm_bias<<<grid, 256>>>(A, W, bias, C, M, N, K, relu);
}

struct EncParams {
    const float *Wq, *bq, *Wk, *bk, *Wv, *bv, *Wo, *bo;
    const float *ln1g, *ln1b, *W1, *b1, *W2, *b2, *ln2g, *ln2b;
};

static void run_encoder(float* x, float* q, float* k, float* v, float* t1, float* t2,
                        const EncParams& p, const int* lens, int M, int Tt)
{
    int ntok = M * Tt;
    for (int l = 0; l < NLAYER; l++) {
        const float* wq = p.Wq + (size_t)l * DMODEL * DMODEL;
        const float* wk = p.Wk + (size_t)l * DMODEL * DMODEL;
        const float* wv = p.Wv + (size_t)l * DMODEL * DMODEL;
        const float* wo = p.Wo + (size_t)l * DMODEL * DMODEL;
        const float* w1 = p.W1 + (size_t)l * DMODEL * FFDIM;
        const float* w2 = p.W2 + (size_t)l * FFDIM * DMODEL;

        gemm(x, wq, p.bq + l * DMODEL, q, ntok, DMODEL, DMODEL, 0);
        gemm(x, wk, p.bk + l * DMODEL, k, ntok, DMODEL, DMODEL, 0);
        gemm(x, wv, p.bv + l * DMODEL, v, ntok, DMODEL, DMODEL, 0);

        attn_kernel<<<M * NHEAD * Tt, 128>>>(q, k, v, t1, lens, Tt);

        gemm(t1, wo, p.bo + l * DMODEL, t2, ntok, DMODEL, DMODEL, 0);
        add_ln_kernel<<<ntok, 128>>>(x, t2, p.ln1g + l * DMODEL, p.ln1b + l * DMODEL, x);

        gemm(x, w1, p.b1 + l * FFDIM, t1, ntok, FFDIM, DMODEL, 1);
        gemm(t1, w2, p.b2 + l * DMODEL, t2, ntok, DMODEL, FFDIM, 0);
        add_ln_kernel<<<ntok, 128>>>(x, t2, p.ln2g + l * DMODEL, p.ln2b + l * DMODEL, x);
    }
}

extern "C" void kernel_launch(void* const* d_in, const int* in_sizes, int n_in,
                              void* d_out, int out_size)
{
    const int*   segment    = (const int*)  d_in[0];
    const int*   prev_hist  = (const int*)  d_in[1];
    const int*   hist_len   = (const int*)  d_in[2];
    const float* sep_img    = (const float*)d_in[3];
    const int*   normalize  = (const int*)  d_in[4];
    const float* embedding  = (const float*)d_in[5];

    EncParams p;
    p.Wq   = (const float*)d_in[6];  p.bq   = (const float*)d_in[7];
    p.Wk   = (const float*)d_in[8];  p.bk   = (const float*)d_in[9];
    p.Wv   = (const float*)d_in[10]; p.bv   = (const float*)d_in[11];
    p.Wo   = (const float*)d_in[12]; p.bo   = (const float*)d_in[13];
    p.ln1g = (const float*)d_in[14]; p.ln1b = (const float*)d_in[15];
    p.W1   = (const float*)d_in[16]; p.b1   = (const float*)d_in[17];
    p.W2   = (const float*)d_in[18]; p.b2   = (const float*)d_in[19];
    p.ln2g = (const float*)d_in[20]; p.ln2b = (const float*)d_in[21];
    const float* Wsep = (const float*)d_in[22];
    const float* bsep = (const float*)d_in[23];

    float *x, *q, *k, *v, *t1, *t2, *hid, *sep;
    cudaGetSymbolAddress((void**)&x,   g_x);
    cudaGetSymbolAddress((void**)&q,   g_q);
    cudaGetSymbolAddress((void**)&k,   g_k);
    cudaGetSymbolAddress((void**)&v,   g_v);
    cudaGetSymbolAddress((void**)&t1,  g_t1);
    cudaGetSymbolAddress((void**)&t2,  g_t2);
    cudaGetSymbolAddress((void**)&hid, g_hidden);
    cudaGetSymbolAddress((void**)&sep, g_sep);

    // ---- main encoder over segment tokens ----
    embed_kernel<<<MAIN_TOK, 128>>>(segment, embedding, x, SLEN);
    run_encoder(x, q, k, v, t1, t2, p, /*lens=*/nullptr, BATCH, SLEN);
    copy_hidden_kernel<<<BATCH, 128>>>(x, hid);

    // ---- separate image projection: (384,2048) @ (2048,512) + b ----
    gemm(sep_img, Wsep, bsep, sep, HIST_SEQ, FFDIM, IMGDIM, 0);

    // ---- history encoder ----
    embed_kernel<<<HIST_TOK, 128>>>(prev_hist, embedding, x, TLEN);
    run_encoder(x, q, k, v, t1, t2, p, hist_len, HIST_SEQ, TLEN);

    // ---- gather last hidden, add to sep, normalize + dot ----
    gather_add_kernel<<<HIST_SEQ, 128>>>(x, hist_len, sep);
    final_kernel<<<HIST_SEQ, 128>>>(sep, hid, normalize, (float*)d_out);
}

// round 3
// speedup vs baseline: 1.3049x; 1.3049x over previous
#include <cuda_runtime.h>
#include <cuda_bf16.h>
#include <math.h>

// Problem constants
#define BATCH 64
#define NSEP  6
#define SLEN  256
#define TLEN  64
#define DMODEL 512
#define NHEAD 4
#define DHEAD 128
#define FFDIM 512
#define NLAYER 4
#define IMGDIM 2048

#define MAIN_TOK (BATCH*SLEN)          // 16384
#define HIST_SEQ (BATCH*NSEP)          // 384
#define HIST_TOK (HIST_SEQ*TLEN)       // 24576
#define MAXTOK   HIST_TOK

// ---------------- scratch (device globals; no allocation allowed) ------------
__device__ float g_x [MAXTOK*DMODEL];
__device__ float g_q [MAXTOK*DMODEL];
__device__ float g_k [MAXTOK*DMODEL];
__device__ float g_v [MAXTOK*DMODEL];
__device__ float g_t1[MAXTOK*DMODEL];
__device__ float g_t2[MAXTOK*DMODEL];
__device__ float g_hidden[BATCH*DMODEL];
__device__ float g_sep[HIST_SEQ*DMODEL];

// =====================================================================
// Tensor-core GEMM: C = A[M,K] @ W[K,N] + bias, optional ReLU.
// Split-bf16 3-term: x = hi + lo (bf16 each) -> Ahi*Bhi + Ahi*Blo + Alo*Bhi.
// Block tile 128x64x16, 256 threads (8 warps: 2 in M x 4 in N).
// Warp tile 64x16 = 4x2 m16n8k16 mma tiles. fp32 accumulate.
// Requires: M%128==0, N%64==0, K%16==0 (true at every call site).
// =====================================================================
#define TBM 128
#define TBN 64
#define TBK 16
#define ASTRIDE 12   // u32 (bf16x2-pair) stride per A row: 8 pairs + 4 pad (conflict-free)
#define BSTRIDE 12   // same for B rows (per n)

__device__ __forceinline__ void bsplit(float v, unsigned short& h, unsigned short& l)
{
    __nv_bfloat16 bh = __float2bfloat16_rn(v);
    float r = v - __bfloat162float(bh);
    __nv_bfloat16 bl = __float2bfloat16_rn(r);
    h = __bfloat16_as_ushort(bh);
    l = __bfloat16_as_ushort(bl);
}

__device__ __forceinline__ void mma16816(float* d, const unsigned* a, const unsigned* b)
{
    asm volatile(
        "mma.sync.aligned.m16n8k16.row.col.f32.bf16.bf16.f32 "
        "{%0,%1,%2,%3},{%4,%5,%6,%7},{%8,%9},{%0,%1,%2,%3};"
        : "+f"(d[0]), "+f"(d[1]), "+f"(d[2]), "+f"(d[3])
        : "r"(a[0]), "r"(a[1]), "r"(a[2]), "r"(a[3]), "r"(b[0]), "r"(b[1]));
}

__global__ __launch_bounds__(256) void gemm_mma(
    const float* __restrict__ A, const float* __restrict__ W,
    const float* __restrict__ bias, float* __restrict__ C,
    int M, int N, int K, int relu)
{
    __shared__ unsigned As_hi[TBM * ASTRIDE];
    __shared__ unsigned As_lo[TBM * ASTRIDE];
    __shared__ unsigned Bs_hi[TBN * BSTRIDE];
    __shared__ unsigned Bs_lo[TBN * BSTRIDE];

    int tid  = threadIdx.x;
    int warp = tid >> 5, lane = tid & 31;
    int wm = warp & 1;          // 2 warps along M
    int wn = warp >> 1;         // 4 warps along N
    int g = lane >> 2, c = lane & 3;

    int brow = blockIdx.y * TBM;
    int bcol = blockIdx.x * TBN;

    float acc[4][2][4];
    #pragma unroll
    for (int mt = 0; mt < 4; mt++)
        #pragma unroll
        for (int nt = 0; nt < 2; nt++)
            #pragma unroll
            for (int i = 0; i < 4; i++) acc[mt][nt][i] = 0.f;

    // B load mapping: k = tid/16 (0..15), nq = tid%16 (float4 along n)
    int b_k = tid >> 4, b_nq = tid & 15;

    for (int k0 = 0; k0 < K; k0 += TBK) {
        // ---- load A tile (128 x 16 fp32 -> split bf16 pairs) ----
        #pragma unroll
        for (int i = 0; i < 2; i++) {
            int idx = tid + 256 * i;          // 0..511
            int row = idx >> 2, kq = idx & 3; // float4 along k
            float4 v = *(const float4*)(A + (size_t)(brow + row) * K + k0 + 4 * kq);
            unsigned short h0,l0,h1,l1,h2,l2,h3,l3;
            bsplit(v.x,h0,l0); bsplit(v.y,h1,l1); bsplit(v.z,h2,l2); bsplit(v.w,h3,l3);
            int base = row * ASTRIDE + 2 * kq;
            As_hi[base]     = (unsigned)h0 | ((unsigned)h1 << 16);
            As_hi[base + 1] = (unsigned)h2 | ((unsigned)h3 << 16);
            As_lo[base]     = (unsigned)l0 | ((unsigned)l1 << 16);
            As_lo[base + 1] = (unsigned)l2 | ((unsigned)l3 << 16);
        }
        // ---- load B tile (16 x 64 fp32 -> transposed split bf16) ----
        {
            float4 v = *(const float4*)(W + (size_t)(k0 + b_k) * N + bcol + 4 * b_nq);
            unsigned short h, l;
            unsigned short* bh16 = (unsigned short*)Bs_hi;
            unsigned short* bl16 = (unsigned short*)Bs_lo;
            int n0 = 4 * b_nq;
            bsplit(v.x,h,l); bh16[(n0+0)*(2*BSTRIDE) + b_k] = h; bl16[(n0+0)*(2*BSTRIDE) + b_k] = l;
            bsplit(v.y,h,l); bh16[(n0+1)*(2*BSTRIDE) + b_k] = h; bl16[(n0+1)*(2*BSTRIDE) + b_k] = l;
            bsplit(v.z,h,l); bh16[(n0+2)*(2*BSTRIDE) + b_k] = h; bl16[(n0+2)*(2*BSTRIDE) + b_k] = l;
            bsplit(v.w,h,l); bh16[(n0+3)*(2*BSTRIDE) + b_k] = h; bl16[(n0+3)*(2*BSTRIDE) + b_k] = l;
        }
        __syncthreads();

        // ---- compute ----
        unsigned bhf[2][2], blf[2][2];
        #pragma unroll
        for (int nt = 0; nt < 2; nt++) {
            int n = wn * 16 + nt * 8 + g;
            bhf[nt][0] = Bs_hi[n * BSTRIDE + c];
            bhf[nt][1] = Bs_hi[n * BSTRIDE + 4 + c];
            blf[nt][0] = Bs_lo[n * BSTRIDE + c];
            blf[nt][1] = Bs_lo[n * BSTRIDE + 4 + c];
        }
        #pragma unroll
        for (int mt = 0; mt < 4; mt++) {
            int r0 = wm * 64 + mt * 16 + g;
            unsigned ah[4], al[4];
            ah[0] = As_hi[r0 * ASTRIDE + c];
            ah[1] = As_hi[(r0 + 8) * ASTRIDE + c];
            ah[2] = As_hi[r0 * ASTRIDE + 4 + c];
            ah[3] = As_hi[(r0 + 8) * ASTRIDE + 4 + c];
            al[0] = As_lo[r0 * ASTRIDE + c];
            al[1] = As_lo[(r0 + 8) * ASTRIDE + c];
            al[2] = As_lo[r0 * ASTRIDE + 4 + c];
            al[3] = As_lo[(r0 + 8) * ASTRIDE + 4 + c];
            #pragma unroll
            for (int nt = 0; nt < 2; nt++) {
                mma16816(acc[mt][nt], ah, bhf[nt]);   // hi*hi
                mma16816(acc[mt][nt], ah, blf[nt]);   // hi*lo
                mma16816(acc[mt][nt], al, bhf[nt]);   // lo*hi
            }
        }
        __syncthreads();
    }

    // ---- epilogue: bias (+relu) + store ----
    #pragma unroll
    for (int mt = 0; mt < 4; mt++) {
        int row = brow + wm * 64 + mt * 16 + g;
        #pragma unroll
        for (int nt = 0; nt < 2; nt++) {
            int col = bcol + wn * 16 + nt * 8 + 2 * c;
            float2 bs = *(const float2*)(bias + col);
            float v0 = acc[mt][nt][0] + bs.x;
            float v1 = acc[mt][nt][1] + bs.y;
            float v2 = acc[mt][nt][2] + bs.x;
            float v3 = acc[mt][nt][3] + bs.y;
            if (relu) {
                v0 = fmaxf(v0, 0.f); v1 = fmaxf(v1, 0.f);
                v2 = fmaxf(v2, 0.f); v3 = fmaxf(v3, 0.f);
            }
            *(float2*)(C + (size_t)row * N + col)       = make_float2(v0, v1);
            *(float2*)(C + (size_t)(row + 8) * N + col) = make_float2(v2, v3);
        }
    }
}

// ---------------- attention: one block per (m, h, q-row), 128 threads --------
__global__ void attn_kernel(const float* __restrict__ q, const float* __restrict__ k,
                            const float* __restrict__ v, float* __restrict__ out,
                            const int* __restrict__ lens, int Tt)
{
    int idx = blockIdx.x;
    int qi = idx % Tt; idx /= Tt;
    int h  = idx % NHEAD; idx /= NHEAD;
    int m  = idx;

    int tid = threadIdx.x;
    int lane = tid & 31, warp = tid >> 5;

    __shared__ float qs[DHEAD];
    __shared__ float sc[SLEN];     // Tt <= 256
    __shared__ float red[4];

    const float* qrow = q + ((size_t)(m * Tt + qi)) * DMODEL + h * DHEAD;
    if (tid < DHEAD) qs[tid] = qrow[tid];
    int valid = Tt;
    if (lens) { int l = lens[m]; valid = l > 1 ? l : 1; }
    __syncthreads();

    // scores: warp per key
    for (int j = warp; j < Tt; j += 4) {
        const float* krow = k + ((size_t)(m * Tt + j)) * DMODEL + h * DHEAD;
        float p = 0.f;
        #pragma unroll
        for (int d = lane; d < DHEAD; d += 32) p += qs[d] * krow[d];
        #pragma unroll
        for (int o = 16; o; o >>= 1) p += __shfl_xor_sync(0xffffffffu, p, o);
        if (lane == 0)
            sc[j] = (j < valid) ? p * 0.08838834764831845f : -1e9f;   // 1/sqrt(128)
    }
    __syncthreads();

    // softmax max
    float mx = -1e30f;
    for (int j = tid; j < Tt; j += 128) mx = fmaxf(mx, sc[j]);
    #pragma unroll
    for (int o = 16; o; o >>= 1) mx = fmaxf(mx, __shfl_xor_sync(0xffffffffu, mx, o));
    if (lane == 0) red[warp] = mx;
    __syncthreads();
    mx = fmaxf(fmaxf(red[0], red[1]), fmaxf(red[2], red[3]));
    __syncthreads();   // protect red reuse

    float sum = 0.f;
    for (int j = tid; j < Tt; j += 128) { float e = __expf(sc[j] - mx); sc[j] = e; sum += e; }
    #pragma unroll
    for (int o = 16; o; o >>= 1) sum += __shfl_xor_sync(0xffffffffu, sum, o);
    if (lane == 0) red[warp] = sum;
    __syncthreads();
    sum = red[0] + red[1] + red[2] + red[3];
    float inv = 1.f / sum;

    // ctx: one channel per thread
    int d = tid;
    if (d < DHEAD) {
        const float* vcol = v + ((size_t)m * Tt) * DMODEL + h * DHEAD + d;
        float acc = 0.f;
        for (int j = 0; j < Tt; j++) acc += sc[j] * vcol[(size_t)j * DMODEL];
        out[((size_t)(m * Tt + qi)) * DMODEL + h * DHEAD + d] = acc * inv;
    }
}

// ---------------- residual add + LayerNorm, block per token -----------------
__global__ void add_ln_kernel(const float* __restrict__ x, const float* __restrict__ y,
                              const float* __restrict__ g, const float* __restrict__ b,
                              float* __restrict__ out)
{
    int t = blockIdx.x, tid = threadIdx.x;
    const float* xr = x + (size_t)t * DMODEL;
    const float* yr = y + (size_t)t * DMODEL;
    int lane = tid & 31, warp = tid >> 5;
    __shared__ float red[4];

    float h[4];
    float s = 0.f;
    #pragma unroll
    for (int i = 0; i < 4; i++) { int d = tid + i * 128; h[i] = xr[d] + yr[d]; s += h[i]; }
    #pragma unroll
    for (int o = 16; o; o >>= 1) s += __shfl_xor_sync(0xffffffffu, s, o);
    if (lane == 0) red[warp] = s;
    __syncthreads();
    s = red[0] + red[1] + red[2] + red[3];
    float mu = s * (1.f / DMODEL);

    float vs = 0.f;
    #pragma unroll
    for (int i = 0; i < 4; i++) { float dl = h[i] - mu; vs += dl * dl; }
    #pragma unroll
    for (int o = 16; o; o >>= 1) vs += __shfl_xor_sync(0xffffffffu, vs, o);
    __syncthreads();   // red reuse
    if (lane == 0) red[warp] = vs;
    __syncthreads();
    vs = (red[0] + red[1] + red[2] + red[3]) * (1.f / DMODEL);
    float invstd = rsqrtf(vs + 1e-5f);

    float* orow = out + (size_t)t * DMODEL;
    #pragma unroll
    for (int i = 0; i < 4; i++) {
        int d = tid + i * 128;
        orow[d] = (h[i] - mu) * invstd * g[d] + b[d];
    }
}

// ---------------- embedding + positional encoding ---------------------------
__device__ __forceinline__ float pe_val(int pos, int d)
{
    int i2 = d & ~1;                       // 2*(d/2)
    float div = expf((float)i2 * (-9.210340371976184f / (float)DMODEL));
    float ang = (float)pos * div;
    return (d & 1) ? cosf(ang) : sinf(ang);
}

__global__ void embed_kernel(const int* __restrict__ ids, const float* __restrict__ emb,
                             float* __restrict__ x, int seqlen)
{
    int tok = blockIdx.x;
    int pos = tok % seqlen;
    int id = ids[tok];
    const float* erow = emb + (size_t)id * DMODEL;
    float* xrow = x + (size_t)tok * DMODEL;
    for (int d = threadIdx.x; d < DMODEL; d += 128)
        xrow[d] = erow[d] + pe_val(pos, d);
}

// ---------------- small epilogue kernels -------------------------------------
__global__ void copy_hidden_kernel(const float* __restrict__ x, float* __restrict__ hid)
{
    int b = blockIdx.x;
    const float* src = x + ((size_t)(b * SLEN + SLEN - 1)) * DMODEL;
    for (int d = threadIdx.x; d < DMODEL; d += 128)
        hid[b * DMODEL + d] = src[d];
}

__global__ void gather_add_kernel(const float* __restrict__ hx, const int* __restrict__ lens,
                                  float* __restrict__ sep)
{
    int r = blockIdx.x;
    int len = lens[r];
    if (len <= 0) return;
    const float* src = hx + ((size_t)(r * TLEN + len - 1)) * DMODEL;
    for (int d = threadIdx.x; d < DMODEL; d += 128)
        sep[(size_t)r * DMODEL + d] += src[d];
}

__global__ void final_kernel(const float* __restrict__ sep, const float* __restrict__ hidden,
                             const int* __restrict__ normalize, float* __restrict__ out)
{
    int r = blockIdx.x;            // 0..383
    int b = r / NSEP;
    int tid = threadIdx.x;
    int lane = tid & 31, warp = tid >> 5;
    int norm = *normalize;

    __shared__ float sbuf[DMODEL];
    __shared__ float red[4];

    for (int d = tid; d < DMODEL; d += 128) {
        float v = sep[(size_t)r * DMODEL + d];
        if (norm) v = fmaxf(v, 0.f);
        sbuf[d] = v;
    }
    __syncthreads();

    float scale = 1.f;
    if (norm) {
        float ss = 0.f;
        for (int d = tid; d < DMODEL; d += 128) ss += sbuf[d] * sbuf[d];
        #pragma unroll
        for (int o = 16; o; o >>= 1) ss += __shfl_xor_sync(0xffffffffu, ss, o);
        if (lane == 0) red[warp] = ss;
        __syncthreads();
        ss = red[0] + red[1] + red[2] + red[3];
        float nrm = sqrtf(ss);
        scale = 1.f / fmaxf(nrm, 1e-12f);
        __syncthreads();   // red reuse below
    }

    float dp = 0.f;
    for (int d = tid; d < DMODEL; d += 128)
        dp += sbuf[d] * scale * hidden[(size_t)b * DMODEL + d];
    #pragma unroll
    for (int o = 16; o; o >>= 1) dp += __shfl_xor_sync(0xffffffffu, dp, o);
    if (lane == 0) red[warp] = dp;
    __syncthreads();
    if (tid == 0) out[r] = red[0] + red[1] + red[2] + red[3];
}

// ---------------- host side ---------------------------------------------------
static void gemm(const float* A, const float* W, const float* bias, float* C,
                 int M, int N, int K, int relu)
{
    dim3 grid(N / TBN, M / TBM);
    gemm_mma<<<grid, 256>>>(A, W, bias, C, M, N, K, relu);
}

struct EncParams {
    const float *Wq, *bq, *Wk, *bk, *Wv, *bv, *Wo, *bo;
    const float *ln1g, *ln1b, *W1, *b1, *W2, *b2, *ln2g, *ln2b;
};

static void run_encoder(float* x, float* q, float* k, float* v, float* t1, float* t2,
                        const EncParams& p, const int* lens, int M, int Tt)
{
    int ntok = M * Tt;
    for (int l = 0; l < NLAYER; l++) {
        const float* wq = p.Wq + (size_t)l * DMODEL * DMODEL;
        const float* wk = p.Wk + (size_t)l * DMODEL * DMODEL;
        const float* wv = p.Wv + (size_t)l * DMODEL * DMODEL;
        const float* wo = p.Wo + (size_t)l * DMODEL * DMODEL;
        const float* w1 = p.W1 + (size_t)l * DMODEL * FFDIM;
        const float* w2 = p.W2 + (size_t)l * FFDIM * DMODEL;

        gemm(x, wq, p.bq + l * DMODEL, q, ntok, DMODEL, DMODEL, 0);
        gemm(x, wk, p.bk + l * DMODEL, k, ntok, DMODEL, DMODEL, 0);
        gemm(x, wv, p.bv + l * DMODEL, v, ntok, DMODEL, DMODEL, 0);

        attn_kernel<<<M * NHEAD * Tt, 128>>>(q, k, v, t1, lens, Tt);

        gemm(t1, wo, p.bo + l * DMODEL, t2, ntok, DMODEL, DMODEL, 0);
        add_ln_kernel<<<ntok, 128>>>(x, t2, p.ln1g + l * DMODEL, p.ln1b + l * DMODEL, x);

        gemm(x, w1, p.b1 + l * FFDIM, t1, ntok, FFDIM, DMODEL, 1);
        gemm(t1, w2, p.b2 + l * DMODEL, t2, ntok, DMODEL, FFDIM, 0);
        add_ln_kernel<<<ntok, 128>>>(x, t2, p.ln2g + l * DMODEL, p.ln2b + l * DMODEL, x);
    }
}

extern "C" void kernel_launch(void* const* d_in, const int* in_sizes, int n_in,
                              void* d_out, int out_size)
{
    const int*   segment    = (const int*)  d_in[0];
    const int*   prev_hist  = (const int*)  d_in[1];
    const int*   hist_len   = (const int*)  d_in[2];
    const float* sep_img    = (const float*)d_in[3];
    const int*   normalize  = (const int*)  d_in[4];
    const float* embedding  = (const float*)d_in[5];

    EncParams p;
    p.Wq   = (const float*)d_in[6];  p.bq   = (const float*)d_in[7];
    p.Wk   = (const float*)d_in[8];  p.bk   = (const float*)d_in[9];
    p.Wv   = (const float*)d_in[10]; p.bv   = (const float*)d_in[11];
    p.Wo   = (const float*)d_in[12]; p.bo   = (const float*)d_in[13];
    p.ln1g = (const float*)d_in[14]; p.ln1b = (const float*)d_in[15];
    p.W1   = (const float*)d_in[16]; p.b1   = (const float*)d_in[17];
    p.W2   = (const float*)d_in[18]; p.b2   = (const float*)d_in[19];
    p.ln2g = (const float*)d_in[20]; p.ln2b = (const float*)d_in[21];
    const float* Wsep = (const float*)d_in[22];
    const float* bsep = (const float*)d_in[23];

    float *x, *q, *k, *v, *t1, *t2, *hid, *sep;
    cudaGetSymbolAddress((void**)&x,   g_x);
    cudaGetSymbolAddress((void**)&q,   g_q);
    cudaGetSymbolAddress((void**)&k,   g_k);
    cudaGetSymbolAddress((void**)&v,   g_v);
    cudaGetSymbolAddress((void**)&t1,  g_t1);
    cudaGetSymbolAddress((void**)&t2,  g_t2);
    cudaGetSymbolAddress((void**)&hid, g_hidden);
    cudaGetSymbolAddress((void**)&sep, g_sep);

    // ---- main encoder over segment tokens ----
    embed_kernel<<<MAIN_TOK, 128>>>(segment, embedding, x, SLEN);
    run_encoder(x, q, k, v, t1, t2, p, /*lens=*/nullptr, BATCH, SLEN);
    copy_hidden_kernel<<<BATCH, 128>>>(x, hid);

    // ---- separate image projection: (384,2048) @ (2048,512) + b ----
    gemm(sep_img, Wsep, bsep, sep, HIST_SEQ, FFDIM, IMGDIM, 0);

    // ---- history encoder ----
    embed_kernel<<<HIST_TOK, 128>>>(prev_hist, embedding, x, TLEN);
    run_encoder(x, q, k, v, t1, t2, p, hist_len, HIST_SEQ, TLEN);

    // ---- gather last hidden, add to sep, normalize + dot ----
    gather_add_kernel<<<HIST_SEQ, 128>>>(x, hist_len, sep);
    final_kernel<<<HIST_SEQ, 128>>>(sep, hid, normalize, (float*)d_out);
}

// round 4
// speedup vs baseline: 1.8044x; 1.3828x over previous
#include <cuda_runtime.h>
#include <cuda_bf16.h>
#include <math.h>

// Problem constants
#define BATCH 64
#define NSEP  6
#define SLEN  256
#define TLEN  64
#define DMODEL 512
#define NHEAD 4
#define DHEAD 128
#define FFDIM 512
#define NLAYER 4
#define IMGDIM 2048

#define MAIN_TOK (BATCH*SLEN)          // 16384
#define HIST_SEQ (BATCH*NSEP)          // 384
#define HIST_TOK (HIST_SEQ*TLEN)       // 24576
#define MAXTOK   HIST_TOK

// ---------------- scratch (device globals; no allocation allowed) ------------
__device__ float g_x [MAXTOK*DMODEL];
__device__ float g_q [MAXTOK*DMODEL];
__device__ float g_k [MAXTOK*DMODEL];
__device__ float g_v [MAXTOK*DMODEL];
__device__ float g_t1[MAXTOK*DMODEL];
__device__ float g_t2[MAXTOK*DMODEL];
__device__ float g_hidden[BATCH*DMODEL];
__device__ float g_sep[HIST_SEQ*DMODEL];

// Pre-split weights (bf16 hi/lo), 7 tensors of 1,048,576 elems each:
// 0:Wq 1:Wk 2:Wv 3:Wo 4:W1 5:W2 6:Wsep
#define WTSZ 1048576
__device__ unsigned short g_whi[7*WTSZ];
__device__ unsigned short g_wlo[7*WTSZ];

__device__ __forceinline__ void bsplit(float v, unsigned short& h, unsigned short& l)
{
    __nv_bfloat16 bh = __float2bfloat16_rn(v);
    float r = v - __bfloat162float(bh);
    __nv_bfloat16 bl = __float2bfloat16_rn(r);
    h = __bfloat16_as_ushort(bh);
    l = __bfloat16_as_ushort(bl);
}

// ---------------- one-time weight split --------------------------------------
__global__ void wsplit_kernel(const float* __restrict__ w, unsigned short* __restrict__ hi,
                              unsigned short* __restrict__ lo, int n4)
{
    int i = blockIdx.x * 256 + threadIdx.x;
    if (i >= n4) return;
    float4 v = ((const float4*)w)[i];
    ushort4 h4, l4;
    bsplit(v.x, h4.x, l4.x);
    bsplit(v.y, h4.y, l4.y);
    bsplit(v.z, h4.z, l4.z);
    bsplit(v.w, h4.w, l4.w);
    ((ushort4*)hi)[i] = h4;
    ((ushort4*)lo)[i] = l4;
}

// =====================================================================
// Tensor-core GEMM: C = A[M,K] @ W[K,N] + bias, optional ReLU.
// A split in-kernel, W pre-split. Software-pipelined k-loop.
// Block tile 128x64x16, 256 threads (8 warps: 2 in M x 4 in N).
// Requires: M%128==0, N%64==0, K%16==0 (true at every call site).
// =====================================================================
#define TBM 128
#define TBN 64
#define TBK 16
#define ASTRIDE 12
#define BSTRIDE 12

__device__ __forceinline__ void mma16816(float* d, const unsigned* a, const unsigned* b)
{
    asm volatile(
        "mma.sync.aligned.m16n8k16.row.col.f32.bf16.bf16.f32 "
        "{%0,%1,%2,%3},{%4,%5,%6,%7},{%8,%9},{%0,%1,%2,%3};"
        : "+f"(d[0]), "+f"(d[1]), "+f"(d[2]), "+f"(d[3])
        : "r"(a[0]), "r"(a[1]), "r"(a[2]), "r"(a[3]), "r"(b[0]), "r"(b[1]));
}

__global__ __launch_bounds__(256) void gemm_mma(
    const float* __restrict__ A,
    const unsigned short* __restrict__ Whi, const unsigned short* __restrict__ Wlo,
    const float* __restrict__ bias, float* __restrict__ C,
    int M, int N, int K, int relu)
{
    __shared__ unsigned As_hi[TBM * ASTRIDE];
    __shared__ unsigned As_lo[TBM * ASTRIDE];
    __shared__ unsigned Bs_hi[TBN * BSTRIDE];
    __shared__ unsigned Bs_lo[TBN * BSTRIDE];

    int tid  = threadIdx.x;
    int warp = tid >> 5, lane = tid & 31;
    int wm = warp & 1;
    int wn = warp >> 1;
    int g = lane >> 2, c = lane & 3;

    int brow = blockIdx.y * TBM;
    int bcol = blockIdx.x * TBN;

    float acc[4][2][4];
    #pragma unroll
    for (int mt = 0; mt < 4; mt++)
        #pragma unroll
        for (int nt = 0; nt < 2; nt++)
            #pragma unroll
            for (int i = 0; i < 4; i++) acc[mt][nt][i] = 0.f;

    // load mappings
    int a_row0 = tid >> 2, a_kq = (tid & 3) << 2;      // two rows: a_row0, a_row0+64
    int b_k = tid >> 4, b_nq = tid & 15;

    const float* aptr0 = A + (size_t)(brow + a_row0) * K + a_kq;
    const float* aptr1 = A + (size_t)(brow + a_row0 + 64) * K + a_kq;
    const unsigned short* bhp = Whi + (size_t)b_k * N + bcol + 4 * b_nq;
    const unsigned short* blp = Wlo + (size_t)b_k * N + bcol + 4 * b_nq;

    // prologue: fetch tile 0
    float4 aReg0 = *(const float4*)(aptr0);
    float4 aReg1 = *(const float4*)(aptr1);
    ushort4 bh = *(const ushort4*)(bhp);
    ushort4 bl = *(const ushort4*)(blp);

    for (int k0 = 0; k0 < K; k0 += TBK) {
        // ---- store staged tile to smem ----
        {
            unsigned short h0,l0,h1,l1,h2,l2,h3,l3;
            bsplit(aReg0.x,h0,l0); bsplit(aReg0.y,h1,l1); bsplit(aReg0.z,h2,l2); bsplit(aReg0.w,h3,l3);
            int base = a_row0 * ASTRIDE + (a_kq >> 1);
            As_hi[base]     = (unsigned)h0 | ((unsigned)h1 << 16);
            As_hi[base + 1] = (unsigned)h2 | ((unsigned)h3 << 16);
            As_lo[base]     = (unsigned)l0 | ((unsigned)l1 << 16);
            As_lo[base + 1] = (unsigned)l2 | ((unsigned)l3 << 16);
            bsplit(aReg1.x,h0,l0); bsplit(aReg1.y,h1,l1); bsplit(aReg1.z,h2,l2); bsplit(aReg1.w,h3,l3);
            base = (a_row0 + 64) * ASTRIDE + (a_kq >> 1);
            As_hi[base]     = (unsigned)h0 | ((unsigned)h1 << 16);
            As_hi[base + 1] = (unsigned)h2 | ((unsigned)h3 << 16);
            As_lo[base]     = (unsigned)l0 | ((unsigned)l1 << 16);
            As_lo[base + 1] = (unsigned)l2 | ((unsigned)l3 << 16);
        }
        {
            unsigned short* bh16 = (unsigned short*)Bs_hi;
            unsigned short* bl16 = (unsigned short*)Bs_lo;
            int n0 = 4 * b_nq;
            bh16[(n0+0)*(2*BSTRIDE) + b_k] = bh.x; bl16[(n0+0)*(2*BSTRIDE) + b_k] = bl.x;
            bh16[(n0+1)*(2*BSTRIDE) + b_k] = bh.y; bl16[(n0+1)*(2*BSTRIDE) + b_k] = bl.y;
            bh16[(n0+2)*(2*BSTRIDE) + b_k] = bh.z; bl16[(n0+2)*(2*BSTRIDE) + b_k] = bl.z;
            bh16[(n0+3)*(2*BSTRIDE) + b_k] = bh.w; bl16[(n0+3)*(2*BSTRIDE) + b_k] = bl.w;
        }
        __syncthreads();

        // ---- prefetch next tile (latency hidden by mma below) ----
        if (k0 + TBK < K) {
            aReg0 = *(const float4*)(aptr0 + k0 + TBK);
            aReg1 = *(const float4*)(aptr1 + k0 + TBK);
            bh = *(const ushort4*)(bhp + (size_t)(k0 + TBK) * N);
            bl = *(const ushort4*)(blp + (size_t)(k0 + TBK) * N);
        }

        // ---- compute ----
        unsigned bhf[2][2], blf[2][2];
        #pragma unroll
        for (int nt = 0; nt < 2; nt++) {
            int n = wn * 16 + nt * 8 + g;
            bhf[nt][0] = Bs_hi[n * BSTRIDE + c];
            bhf[nt][1] = Bs_hi[n * BSTRIDE + 4 + c];
            blf[nt][0] = Bs_lo[n * BSTRIDE + c];
            blf[nt][1] = Bs_lo[n * BSTRIDE + 4 + c];
        }
        #pragma unroll
        for (int mt = 0; mt < 4; mt++) {
            int r0 = wm * 64 + mt * 16 + g;
            unsigned ah[4], al[4];
            ah[0] = As_hi[r0 * ASTRIDE + c];
            ah[1] = As_hi[(r0 + 8) * ASTRIDE + c];
            ah[2] = As_hi[r0 * ASTRIDE + 4 + c];
            ah[3] = As_hi[(r0 + 8) * ASTRIDE + 4 + c];
            al[0] = As_lo[r0 * ASTRIDE + c];
            al[1] = As_lo[(r0 + 8) * ASTRIDE + c];
            al[2] = As_lo[r0 * ASTRIDE + 4 + c];
            al[3] = As_lo[(r0 + 8) * ASTRIDE + 4 + c];
            #pragma unroll
            for (int nt = 0; nt < 2; nt++) {
                mma16816(acc[mt][nt], ah, bhf[nt]);
                mma16816(acc[mt][nt], ah, blf[nt]);
                mma16816(acc[mt][nt], al, bhf[nt]);
            }
        }
        __syncthreads();
    }

    // ---- epilogue ----
    #pragma unroll
    for (int mt = 0; mt < 4; mt++) {
        int row = brow + wm * 64 + mt * 16 + g;
        #pragma unroll
        for (int nt = 0; nt < 2; nt++) {
            int col = bcol + wn * 16 + nt * 8 + 2 * c;
            float2 bs = *(const float2*)(bias + col);
            float v0 = acc[mt][nt][0] + bs.x;
            float v1 = acc[mt][nt][1] + bs.y;
            float v2 = acc[mt][nt][2] + bs.x;
            float v3 = acc[mt][nt][3] + bs.y;
            if (relu) {
                v0 = fmaxf(v0, 0.f); v1 = fmaxf(v1, 0.f);
                v2 = fmaxf(v2, 0.f); v3 = fmaxf(v3, 0.f);
            }
            *(float2*)(C + (size_t)row * N + col)       = make_float2(v0, v1);
            *(float2*)(C + (size_t)(row + 8) * N + col) = make_float2(v2, v3);
        }
    }
}

// =====================================================================
// Attention v2: block per (seq m, head h, 64-row q-tile), 256 threads.
// K/V streamed through smem in 64-key chunks; scores resident in smem.
// Requires Tt % 64 == 0 (256, 64).
// =====================================================================
#define QT 64
#define KC 64
#define QSTR 129   // odd stride: conflict-light scalar access
#define KSTR 129
#define VSTR 132   // %4: float4-friendly

__global__ __launch_bounds__(256) void attn2_kernel(
    const float* __restrict__ q, const float* __restrict__ k,
    const float* __restrict__ v, float* __restrict__ out,
    const int* __restrict__ lens, int Tt, int nQT)
{
    extern __shared__ float sm[];
    float* Qs  = sm;                       // QT x QSTR
    float* KVs = Qs + QT * QSTR;           // KC x VSTR (shared by K and V phases)
    float* SC  = KVs + KC * VSTR;          // QT x (Tt+1)

    int tid = threadIdx.x;
    int b = blockIdx.x;
    int qt  = b % nQT; int rem = b / nQT;
    int h = rem % NHEAD; int m = rem / NHEAD;
    int q0 = qt * QT;
    int sstr = Tt + 1;

    int valid = Tt;
    if (lens) { int l = lens[m]; valid = l > 1 ? l : 1; }

    // ---- load Q tile ----
    const float* qbase = q + ((size_t)m * Tt + q0) * DMODEL + h * DHEAD;
    for (int i = tid; i < QT * (DHEAD/4); i += 256) {
        int row = i >> 5, c4 = i & 31;
        float4 vq = *(const float4*)(qbase + (size_t)row * DMODEL + 4 * c4);
        float* dst = Qs + row * QSTR + 4 * c4;
        dst[0] = vq.x; dst[1] = vq.y; dst[2] = vq.z; dst[3] = vq.w;
    }

    // ---- phase 1: raw scores ----
    int tq = (tid >> 4) << 2;    // 0..60
    int tk = (tid & 15) << 2;    // 0..60
    for (int kc = 0; kc < Tt; kc += KC) {
        __syncthreads();
        const float* kbase = k + ((size_t)m * Tt + kc) * DMODEL + h * DHEAD;
        for (int i = tid; i < KC * (DHEAD/4); i += 256) {
            int row = i >> 5, c4 = i & 31;
            float4 vk = *(const float4*)(kbase + (size_t)row * DMODEL + 4 * c4);
            float* dst = KVs + row * KSTR + 4 * c4;
            dst[0] = vk.x; dst[1] = vk.y; dst[2] = vk.z; dst[3] = vk.w;
        }
        __syncthreads();

        float acc[4][4];
        #pragma unroll
        for (int i = 0; i < 4; i++)
            #pragma unroll
            for (int j = 0; j < 4; j++) acc[i][j] = 0.f;

        const float* qp0 = Qs + (tq + 0) * QSTR;
        const float* qp1 = Qs + (tq + 1) * QSTR;
        const float* qp2 = Qs + (tq + 2) * QSTR;
        const float* qp3 = Qs + (tq + 3) * QSTR;
        const float* kp0 = KVs + (tk + 0) * KSTR;
        const float* kp1 = KVs + (tk + 1) * KSTR;
        const float* kp2 = KVs + (tk + 2) * KSTR;
        const float* kp3 = KVs + (tk + 3) * KSTR;

        #pragma unroll 4
        for (int d = 0; d < DHEAD; d++) {
            float qa[4] = { qp0[d], qp1[d], qp2[d], qp3[d] };
            float kb[4] = { kp0[d], kp1[d], kp2[d], kp3[d] };
            #pragma unroll
            for (int i = 0; i < 4; i++)
                #pragma unroll
                for (int j = 0; j < 4; j++)
                    acc[i][j] += qa[i] * kb[j];
        }
        #pragma unroll
        for (int i = 0; i < 4; i++)
            #pragma unroll
            for (int j = 0; j < 4; j++)
                SC[(tq + i) * sstr + kc + tk + j] = acc[i][j];
    }
    __syncthreads();

    // ---- phase 2: softmax per row (warp w owns rows 8w..8w+7) ----
    {
        int warp = tid >> 5, lane = tid & 31;
        const float scale = 0.08838834764831845f;   // 1/sqrt(128)
        for (int rr = 0; rr < 8; rr++) {
            float* row = SC + (warp * 8 + rr) * sstr;
            float mx = -1e30f;
            for (int j = lane; j < Tt; j += 32) {
                float s = (j < valid) ? row[j] * scale : -1e9f;
                row[j] = s;
                mx = fmaxf(mx, s);
            }
            #pragma unroll
            for (int o = 16; o; o >>= 1) mx = fmaxf(mx, __shfl_xor_sync(0xffffffffu, mx, o));
            float sum = 0.f;
            for (int j = lane; j < Tt; j += 32) {
                float e = __expf(row[j] - mx);
                row[j] = e;
                sum += e;
            }
            #pragma unroll
            for (int o = 16; o; o >>= 1) sum += __shfl_xor_sync(0xffffffffu, sum, o);
            float inv = 1.f / sum;
            for (int j = lane; j < Tt; j += 32) row[j] *= inv;
        }
    }

    // ---- phase 3: P @ V ----
    int tqg = (tid >> 4) << 2;   // 4 q-rows
    int td  = (tid & 15) << 3;   // 8 d-channels
    float cacc[4][8];
    #pragma unroll
    for (int i = 0; i < 4; i++)
        #pragma unroll
        for (int j = 0; j < 8; j++) cacc[i][j] = 0.f;

    for (int kc = 0; kc < Tt; kc += KC) {
        __syncthreads();    // softmax done / prev chunk compute done
        const float* vbase = v + ((size_t)m * Tt + kc) * DMODEL + h * DHEAD;
        for (int i = tid; i < KC * (DHEAD/4); i += 256) {
            int row = i >> 5, c4 = i & 31;
            float4 vv = *(const float4*)(vbase + (size_t)row * DMODEL + 4 * c4);
            *(float4*)(KVs + row * VSTR + 4 * c4) = vv;
        }
        __syncthreads();

        const float* pp0 = SC + (tqg + 0) * sstr + kc;
        const float* pp1 = SC + (tqg + 1) * sstr + kc;
        const float* pp2 = SC + (tqg + 2) * sstr + kc;
        const float* pp3 = SC + (tqg + 3) * sstr + kc;
        #pragma unroll 2
        for (int kk = 0; kk < KC; kk++) {
            float p[4] = { pp0[kk], pp1[kk], pp2[kk], pp3[kk] };
            float4 v0 = *(const float4*)(KVs + kk * VSTR + td);
            float4 v1 = *(const float4*)(KVs + kk * VSTR + td + 4);
            float vv[8] = { v0.x, v0.y, v0.z, v0.w, v1.x, v1.y, v1.z, v1.w };
            #pragma unroll
            for (int i = 0; i < 4; i++)
                #pragma unroll
                for (int j = 0; j < 8; j++)
                    cacc[i][j] += p[i] * vv[j];
        }
    }

    // ---- store ctx ----
    float* obase = out + ((size_t)m * Tt + q0) * DMODEL + h * DHEAD;
    #pragma unroll
    for (int i = 0; i < 4; i++) {
        float* orow = obase + (size_t)(tqg + i) * DMODEL + td;
        *(float4*)(orow)     = make_float4(cacc[i][0], cacc[i][1], cacc[i][2], cacc[i][3]);
        *(float4*)(orow + 4) = make_float4(cacc[i][4], cacc[i][5], cacc[i][6], cacc[i][7]);
    }
}

// ---------------- residual add + LayerNorm, block per token -----------------
__global__ void add_ln_kernel(const float* __restrict__ x, const float* __restrict__ y,
                              const float* __restrict__ g, const float* __restrict__ b,
                              float* __restrict__ out)
{
    int t = blockIdx.x, tid = threadIdx.x;
    const float* xr = x + (size_t)t * DMODEL;
    const float* yr = y + (size_t)t * DMODEL;
    int lane = tid & 31, warp = tid >> 5;
    __shared__ float red[4];

    float h[4];
    float s = 0.f;
    #pragma unroll
    for (int i = 0; i < 4; i++) { int d = tid + i * 128; h[i] = xr[d] + yr[d]; s += h[i]; }
    #pragma unroll
    for (int o = 16; o; o >>= 1) s += __shfl_xor_sync(0xffffffffu, s, o);
    if (lane == 0) red[warp] = s;
    __syncthreads();
    s = red[0] + red[1] + red[2] + red[3];
    float mu = s * (1.f / DMODEL);

    float vs = 0.f;
    #pragma unroll
    for (int i = 0; i < 4; i++) { float dl = h[i] - mu; vs += dl * dl; }
    #pragma unroll
    for (int o = 16; o; o >>= 1) vs += __shfl_xor_sync(0xffffffffu, vs, o);
    __syncthreads();
    if (lane == 0) red[warp] = vs;
    __syncthreads();
    vs = (red[0] + red[1] + red[2] + red[3]) * (1.f / DMODEL);
    float invstd = rsqrtf(vs + 1e-5f);

    float* orow = out + (size_t)t * DMODEL;
    #pragma unroll
    for (int i = 0; i < 4; i++) {
        int d = tid + i * 128;
        orow[d] = (h[i] - mu) * invstd * g[d] + b[d];
    }
}

// ---------------- embedding + positional encoding ---------------------------
__device__ __forceinline__ float pe_val(int pos, int d)
{
    int i2 = d & ~1;
    float div = expf((float)i2 * (-9.210340371976184f / (float)DMODEL));
    float ang = (float)pos * div;
    return (d & 1) ? cosf(ang) : sinf(ang);
}

__global__ void embed_kernel(const int* __restrict__ ids, const float* __restrict__ emb,
                             float* __restrict__ x, int seqlen)
{
    int tok = blockIdx.x;
    int pos = tok % seqlen;
    int id = ids[tok];
    const float* erow = emb + (size_t)id * DMODEL;
    float* xrow = x + (size_t)tok * DMODEL;
    for (int d = threadIdx.x; d < DMODEL; d += 128)
        xrow[d] = erow[d] + pe_val(pos, d);
}

// ---------------- small epilogue kernels -------------------------------------
__global__ void copy_hidden_kernel(const float* __restrict__ x, float* __restrict__ hid)
{
    int b = blockIdx.x;
    const float* src = x + ((size_t)(b * SLEN + SLEN - 1)) * DMODEL;
    for (int d = threadIdx.x; d < DMODEL; d += 128)
        hid[b * DMODEL + d] = src[d];
}

__global__ void gather_add_kernel(const float* __restrict__ hx, const int* __restrict__ lens,
                                  float* __restrict__ sep)
{
    int r = blockIdx.x;
    int len = lens[r];
    if (len <= 0) return;
    const float* src = hx + ((size_t)(r * TLEN + len - 1)) * DMODEL;
    for (int d = threadIdx.x; d < DMODEL; d += 128)
        sep[(size_t)r * DMODEL + d] += src[d];
}

__global__ void final_kernel(const float* __restrict__ sep, const float* __restrict__ hidden,
                             const int* __restrict__ normalize, float* __restrict__ out)
{
    int r = blockIdx.x;
    int b = r / NSEP;
    int tid = threadIdx.x;
    int lane = tid & 31, warp = tid >> 5;
    int norm = *normalize;

    __shared__ float sbuf[DMODEL];
    __shared__ float red[4];

    for (int d = tid; d < DMODEL; d += 128) {
        float v = sep[(size_t)r * DMODEL + d];
        if (norm) v = fmaxf(v, 0.f);
        sbuf[d] = v;
    }
    __syncthreads();

    float scale = 1.f;
    if (norm) {
        float ss = 0.f;
        for (int d = tid; d < DMODEL; d += 128) ss += sbuf[d] * sbuf[d];
        #pragma unroll
        for (int o = 16; o; o >>= 1) ss += __shfl_xor_sync(0xffffffffu, ss, o);
        if (lane == 0) red[warp] = ss;
        __syncthreads();
        ss = red[0] + red[1] + red[2] + red[3];
        float nrm = sqrtf(ss);
        scale = 1.f / fmaxf(nrm, 1e-12f);
        __syncthreads();
    }

    float dp = 0.f;
    for (int d = tid; d < DMODEL; d += 128)
        dp += sbuf[d] * scale * hidden[(size_t)b * DMODEL + d];
    #pragma unroll
    for (int o = 16; o; o >>= 1) dp += __shfl_xor_sync(0xffffffffu, dp, o);
    if (lane == 0) red[warp] = dp;
    __syncthreads();
    if (tid == 0) out[r] = red[0] + red[1] + red[2] + red[3];
}

// ---------------- host side ---------------------------------------------------
static void gemm(const float* A, const unsigned short* Whi, const unsigned short* Wlo,
                 const float* bias, float* C, int M, int N, int K, int relu)
{
    dim3 grid(N / TBN, M / TBM);
    gemm_mma<<<grid, 256>>>(A, Whi, Wlo, bias, C, M, N, K, relu);
}

struct EncParams {
    const unsigned short *whi, *wlo;     // base of pre-split weight arrays
    const float *bq, *bk, *bv, *bo;
    const float *ln1g, *ln1b, *b1, *b2, *ln2g, *ln2b;
};

static void launch_attn(const float* q, const float* k, const float* v, float* out,
                        const int* lens, int M, int Tt)
{
    int nQT = Tt / QT;
    int grid = M * NHEAD * nQT;
    size_t smem = (size_t)(QT * QSTR + KC * VSTR + QT * (Tt + 1)) * sizeof(float);
    attn2_kernel<<<grid, 256, smem>>>(q, k, v, out, lens, Tt, nQT);
}

static void run_encoder(float* x, float* q, float* k, float* v, float* t1, float* t2,
                        const EncParams& p, const int* lens, int M, int Tt)
{
    int ntok = M * Tt;
    const int LW = DMODEL * DMODEL;   // 262144
    for (int l = 0; l < NLAYER; l++) {
        const unsigned short* wq_h = p.whi + 0*WTSZ + (size_t)l * LW;
        const unsigned short* wq_l = p.wlo + 0*WTSZ + (size_t)l * LW;
        const unsigned short* wk_h = p.whi + 1*WTSZ + (size_t)l * LW;
        const unsigned short* wk_l = p.wlo + 1*WTSZ + (size_t)l * LW;
        const unsigned short* wv_h = p.whi + 2*WTSZ + (size_t)l * LW;
        const unsigned short* wv_l = p.wlo + 2*WTSZ + (size_t)l * LW;
        const unsigned short* wo_h = p.whi + 3*WTSZ + (size_t)l * LW;
        const unsigned short* wo_l = p.wlo + 3*WTSZ + (size_t)l * LW;
        const unsigned short* w1_h = p.whi + 4*WTSZ + (size_t)l * LW;
        const unsigned short* w1_l = p.wlo + 4*WTSZ + (size_t)l * LW;
        const unsigned short* w2_h = p.whi + 5*WTSZ + (size_t)l * LW;
        const unsigned short* w2_l = p.wlo + 5*WTSZ + (size_t)l * LW;

        gemm(x, wq_h, wq_l, p.bq + l * DMODEL, q, ntok, DMODEL, DMODEL, 0);
        gemm(x, wk_h, wk_l, p.bk + l * DMODEL, k, ntok, DMODEL, DMODEL, 0);
        gemm(x, wv_h, wv_l, p.bv + l * DMODEL, v, ntok, DMODEL, DMODEL, 0);

        launch_attn(q, k, v, t1, lens, M, Tt);

        gemm(t1, wo_h, wo_l, p.bo + l * DMODEL, t2, ntok, DMODEL, DMODEL, 0);
        add_ln_kernel<<<ntok, 128>>>(x, t2, p.ln1g + l * DMODEL, p.ln1b + l * DMODEL, x);

        gemm(x, w1_h, w1_l, p.b1 + l * FFDIM, t1, ntok, FFDIM, DMODEL, 1);
        gemm(t1, w2_h, w2_l, p.b2 + l * DMODEL, t2, ntok, DMODEL, FFDIM, 0);
        add_ln_kernel<<<ntok, 128>>>(x, t2, p.ln2g + l * DMODEL, p.ln2b + l * DMODEL, x);
    }
}

extern "C" void kernel_launch(void* const* d_in, const int* in_sizes, int n_in,
                              void* d_out, int out_size)
{
    const int*   segment    = (const int*)  d_in[0];
    const int*   prev_hist  = (const int*)  d_in[1];
    const int*   hist_len   = (const int*)  d_in[2];
    const float* sep_img    = (const float*)d_in[3];
    const int*   normalize  = (const int*)  d_in[4];
    const float* embedding  = (const float*)d_in[5];

    const float* Wq   = (const float*)d_in[6];  const float* bq   = (const float*)d_in[7];
    const float* Wk   = (const float*)d_in[8];  const float* bk   = (const float*)d_in[9];
    const float* Wv   = (const float*)d_in[10]; const float* bv   = (const float*)d_in[11];
    const float* Wo   = (const float*)d_in[12]; const float* bo   = (const float*)d_in[13];
    const float* ln1g = (const float*)d_in[14]; const float* ln1b = (const float*)d_in[15];
    const float* W1   = (const float*)d_in[16]; const float* b1   = (const float*)d_in[17];
    const float* W2   = (const float*)d_in[18]; const float* b2   = (const float*)d_in[19];
    const float* ln2g = (const float*)d_in[20]; const float* ln2b = (const float*)d_in[21];
    const float* Wsep = (const float*)d_in[22];
    const float* bsep = (const float*)d_in[23];

    float *x, *q, *k, *v, *t1, *t2, *hid, *sep;
    unsigned short *whi, *wlo;
    cudaGetSymbolAddress((void**)&x,   g_x);
    cudaGetSymbolAddress((void**)&q,   g_q);
    cudaGetSymbolAddress((void**)&k,   g_k);
    cudaGetSymbolAddress((void**)&v,   g_v);
    cudaGetSymbolAddress((void**)&t1,  g_t1);
    cudaGetSymbolAddress((void**)&t2,  g_t2);
    cudaGetSymbolAddress((void**)&hid, g_hidden);
    cudaGetSymbolAddress((void**)&sep, g_sep);
    cudaGetSymbolAddress((void**)&whi, g_whi);
    cudaGetSymbolAddress((void**)&wlo, g_wlo);

    // allow big dynamic smem for attention (idempotent)
    cudaFuncSetAttribute(attn2_kernel, cudaFuncAttributeMaxDynamicSharedMemorySize, 140 * 1024);

    // ---- pre-split all weights ----
    {
        const float* srcs[7] = { Wq, Wk, Wv, Wo, W1, W2, Wsep };
        for (int t = 0; t < 7; t++) {
            int n4 = WTSZ / 4;
            wsplit_kernel<<<(n4 + 255) / 256, 256>>>(srcs[t], whi + (size_t)t * WTSZ,
                                                     wlo + (size_t)t * WTSZ, n4);
        }
    }

    EncParams p;
    p.whi = whi; p.wlo = wlo;
    p.bq = bq; p.bk = bk; p.bv = bv; p.bo = bo;
    p.ln1g = ln1g; p.ln1b = ln1b; p.b1 = b1; p.b2 = b2; p.ln2g = ln2g; p.ln2b = ln2b;

    // ---- main encoder ----
    embed_kernel<<<MAIN_TOK, 128>>>(segment, embedding, x, SLEN);
    run_encoder(x, q, k, v, t1, t2, p, nullptr, BATCH, SLEN);
    copy_hidden_kernel<<<BATCH, 128>>>(x, hid);

    // ---- separate image projection: (384,2048) @ (2048,512) + b ----
    gemm(sep_img, whi + (size_t)6 * WTSZ, wlo + (size_t)6 * WTSZ, bsep, sep,
         HIST_SEQ, FFDIM, IMGDIM, 0);

    // ---- history encoder ----
    embed_kernel<<<HIST_TOK, 128>>>(prev_hist, embedding, x, TLEN);
    run_encoder(x, q, k, v, t1, t2, p, hist_len, HIST_SEQ, TLEN);

    // ---- gather last hidden, add to sep, normalize + dot ----
    gather_add_kernel<<<HIST_SEQ, 128>>>(x, hist_len, sep);
    final_kernel<<<HIST_SEQ, 128>>>(sep, hid, normalize, (float*)d_out);
}